// round 1
// baseline (speedup 1.0000x reference)
#include <cuda_runtime.h>
#include <math.h>

#define Bb 4
#define Ss 2048
#define Dd 512
#define Hh 8
#define DHh 64

// ---------------- scratch (static device allocations are allowed) ----------
__device__ float g_xn [Bb*Ss*Dd];
__device__ float g_q  [Bb*Ss*Dd];
__device__ float g_k  [Bb*Ss*Dd];
__device__ float g_v  [Bb*Ss*Dd];
__device__ float g_ctx[Bb*Ss*Dd];
__device__ float g_pe [Ss*Dd];
__device__ float g_pos[Ss*Dd];
__device__ float g_ps [(size_t)Bb*Hh*Ss*Ss];   // 512 MB
__device__ float g_sc [(size_t)Bb*Hh*Ss*Ss];   // 512 MB

// ---------------- sinusoidal positional encoding ---------------------------
__global__ void pe_kernel(float* __restrict__ pe) {
    int idx = blockIdx.x * blockDim.x + threadIdx.x;   // S*D/2 total
    int s = idx >> 8;          // D/2 = 256
    int i = idx & 255;
    // div = exp(2i * (-ln(10000)/512))
    float div = expf((2.0f * (float)i) * (-9.210340371976184f / 512.0f));
    float a = (float)s * div;
    pe[s * Dd + 2 * i]     = sinf(a);
    pe[s * Dd + 2 * i + 1] = cosf(a);
}

// ---------------- layernorm -------------------------------------------------
__global__ void ln_kernel(const float* __restrict__ x,
                          const float* __restrict__ gamma,
                          const float* __restrict__ beta,
                          float* __restrict__ out) {
    int row = blockIdx.x;                 // B*S rows
    const float2* xr = (const float2*)(x + (size_t)row * Dd);
    int t = threadIdx.x;                  // 256 threads, 2 elems each
    float2 v = xr[t];
    float s1 = v.x + v.y;
    float s2 = v.x * v.x + v.y * v.y;
    #pragma unroll
    for (int o = 16; o; o >>= 1) {
        s1 += __shfl_xor_sync(0xffffffffu, s1, o);
        s2 += __shfl_xor_sync(0xffffffffu, s2, o);
    }
    __shared__ float r1[8], r2[8];
    if ((t & 31) == 0) { r1[t >> 5] = s1; r2[t >> 5] = s2; }
    __syncthreads();
    float S1 = 0.f, S2 = 0.f;
    #pragma unroll
    for (int i = 0; i < 8; i++) { S1 += r1[i]; S2 += r2[i]; }
    float mean = S1 * (1.0f / 512.0f);
    float var  = S2 * (1.0f / 512.0f) - mean * mean;
    float rstd = rsqrtf(var + 1e-5f);
    float2 g  = ((const float2*)gamma)[t];
    float2 bt = ((const float2*)beta)[t];
    float2 o2;
    o2.x = (v.x - mean) * rstd * g.x + bt.x;
    o2.y = (v.y - mean) * rstd * g.y + bt.y;
    ((float2*)(out + (size_t)row * Dd))[t] = o2;
}

// ---------------- generic C = A @ W^T + bias (row-major, K-contig) ----------
// A[M,K], W[N,K], C[M,N]. BM=BN=64, BK=16, 256 threads, 4x4 per thread.
__global__ void gemm_nt_bias(const float* __restrict__ A,
                             const float* __restrict__ W,
                             const float* __restrict__ bias,
                             float* __restrict__ C,
                             int M, int N, int K) {
    __shared__ float As[16][64];
    __shared__ float Bs[16][64];
    const int t  = threadIdx.x;
    const int tx = t & 15, ty = t >> 4;
    const int m0 = blockIdx.y * 64, n0 = blockIdx.x * 64;
    const int lrow = t >> 2, lq = t & 3;
    float acc[4][4] = {};
    const float* Ap = A + (size_t)(m0 + lrow) * K + lq * 4;
    const float* Wp = W + (size_t)(n0 + lrow) * K + lq * 4;
    for (int k0 = 0; k0 < K; k0 += 16) {
        float4 av = *(const float4*)(Ap + k0);
        float4 wv = *(const float4*)(Wp + k0);
        As[lq*4+0][lrow] = av.x; As[lq*4+1][lrow] = av.y;
        As[lq*4+2][lrow] = av.z; As[lq*4+3][lrow] = av.w;
        Bs[lq*4+0][lrow] = wv.x; Bs[lq*4+1][lrow] = wv.y;
        Bs[lq*4+2][lrow] = wv.z; Bs[lq*4+3][lrow] = wv.w;
        __syncthreads();
        #pragma unroll
        for (int kk = 0; kk < 16; kk++) {
            float4 a = *(const float4*)&As[kk][ty * 4];
            float4 b = *(const float4*)&Bs[kk][tx * 4];
            acc[0][0]+=a.x*b.x; acc[0][1]+=a.x*b.y; acc[0][2]+=a.x*b.z; acc[0][3]+=a.x*b.w;
            acc[1][0]+=a.y*b.x; acc[1][1]+=a.y*b.y; acc[1][2]+=a.y*b.z; acc[1][3]+=a.y*b.w;
            acc[2][0]+=a.z*b.x; acc[2][1]+=a.z*b.y; acc[2][2]+=a.z*b.z; acc[2][3]+=a.z*b.w;
            acc[3][0]+=a.w*b.x; acc[3][1]+=a.w*b.y; acc[3][2]+=a.w*b.z; acc[3][3]+=a.w*b.w;
        }
        __syncthreads();
    }
    #pragma unroll
    for (int i = 0; i < 4; i++) {
        float* Cr = C + (size_t)(m0 + ty * 4 + i) * N + n0 + tx * 4;
        #pragma unroll
        for (int j = 0; j < 4; j++) {
            float bv = bias ? bias[n0 + tx * 4 + j] : 0.0f;
            Cr[j] = acc[i][j] + bv;
        }
    }
}

// ---------------- PS = (q + v_bias) . pos^T  per (b,h) ----------------------
// q[b,s,h,d] layout: ((b*S+s)*512 + h*64 + d); pos: (t*512 + h*64 + d)
__global__ void ps_kernel(const float* __restrict__ q,
                          const float* __restrict__ pos,
                          const float* __restrict__ vbias,
                          float* __restrict__ ps) {
    const int bh = blockIdx.z, b = bh >> 3, h = bh & 7;
    const int s0 = blockIdx.y * 64, t0 = blockIdx.x * 64;
    __shared__ float Qs[64][64];   // [d][s]
    __shared__ float Ks[64][64];   // [d][t]
    const int t  = threadIdx.x;
    const int tx = t & 15, ty = t >> 4;
    const int lrow = t >> 2, lq = t & 3;
    const float* qp = q   + ((size_t)(b * Ss + s0 + lrow)) * Dd + h * 64;
    const float* pp = pos + ((size_t)(t0 + lrow)) * Dd + h * 64;
    const float* vb = vbias + h * 64;
    #pragma unroll
    for (int j = 0; j < 4; j++) {
        int c4 = lq * 4 + j;
        float4 qv = *(const float4*)(qp + c4 * 4);
        float4 bv = *(const float4*)(vb + c4 * 4);
        Qs[c4*4+0][lrow] = qv.x + bv.x; Qs[c4*4+1][lrow] = qv.y + bv.y;
        Qs[c4*4+2][lrow] = qv.z + bv.z; Qs[c4*4+3][lrow] = qv.w + bv.w;
        float4 pv = *(const float4*)(pp + c4 * 4);
        Ks[c4*4+0][lrow] = pv.x; Ks[c4*4+1][lrow] = pv.y;
        Ks[c4*4+2][lrow] = pv.z; Ks[c4*4+3][lrow] = pv.w;
    }
    __syncthreads();
    float acc[4][4] = {};
    #pragma unroll
    for (int kk = 0; kk < 64; kk++) {
        float4 a = *(const float4*)&Qs[kk][ty * 4];
        float4 b = *(const float4*)&Ks[kk][tx * 4];
        acc[0][0]+=a.x*b.x; acc[0][1]+=a.x*b.y; acc[0][2]+=a.x*b.z; acc[0][3]+=a.x*b.w;
        acc[1][0]+=a.y*b.x; acc[1][1]+=a.y*b.y; acc[1][2]+=a.y*b.z; acc[1][3]+=a.y*b.w;
        acc[2][0]+=a.z*b.x; acc[2][1]+=a.z*b.y; acc[2][2]+=a.z*b.z; acc[2][3]+=a.z*b.w;
        acc[3][0]+=a.w*b.x; acc[3][1]+=a.w*b.y; acc[3][2]+=a.w*b.z; acc[3][3]+=a.w*b.w;
    }
    #pragma unroll
    for (int i = 0; i < 4; i++) {
        float* o = ps + ((size_t)bh * Ss + (s0 + ty * 4 + i)) * Ss + t0 + tx * 4;
        #pragma unroll
        for (int j = 0; j < 4; j++) o[j] = acc[i][j];
    }
}

// ---------------- score = ((q+u).k^T + rel_shift(PS)) / sqrt(D) -------------
__global__ void score_kernel(const float* __restrict__ q,
                             const float* __restrict__ k,
                             const float* __restrict__ ubias,
                             const float* __restrict__ ps,
                             float* __restrict__ sc) {
    const int bh = blockIdx.z, b = bh >> 3, h = bh & 7;
    const int s0 = blockIdx.y * 64, t0 = blockIdx.x * 64;
    __shared__ float Qs[64][64];
    __shared__ float Ks[64][64];
    const int t  = threadIdx.x;
    const int tx = t & 15, ty = t >> 4;
    const int lrow = t >> 2, lq = t & 3;
    const float* qp = q + ((size_t)(b * Ss + s0 + lrow)) * Dd + h * 64;
    const float* kp = k + ((size_t)(b * Ss + t0 + lrow)) * Dd + h * 64;
    const float* ub = ubias + h * 64;
    #pragma unroll
    for (int j = 0; j < 4; j++) {
        int c4 = lq * 4 + j;
        float4 qv = *(const float4*)(qp + c4 * 4);
        float4 bv = *(const float4*)(ub + c4 * 4);
        Qs[c4*4+0][lrow] = qv.x + bv.x; Qs[c4*4+1][lrow] = qv.y + bv.y;
        Qs[c4*4+2][lrow] = qv.z + bv.z; Qs[c4*4+3][lrow] = qv.w + bv.w;
        float4 kv = *(const float4*)(kp + c4 * 4);
        Ks[c4*4+0][lrow] = kv.x; Ks[c4*4+1][lrow] = kv.y;
        Ks[c4*4+2][lrow] = kv.z; Ks[c4*4+3][lrow] = kv.w;
    }
    __syncthreads();
    float acc[4][4] = {};
    #pragma unroll
    for (int kk = 0; kk < 64; kk++) {
        float4 a = *(const float4*)&Qs[kk][ty * 4];
        float4 b = *(const float4*)&Ks[kk][tx * 4];
        acc[0][0]+=a.x*b.x; acc[0][1]+=a.x*b.y; acc[0][2]+=a.x*b.z; acc[0][3]+=a.x*b.w;
        acc[1][0]+=a.y*b.x; acc[1][1]+=a.y*b.y; acc[1][2]+=a.y*b.z; acc[1][3]+=a.y*b.w;
        acc[2][0]+=a.z*b.x; acc[2][1]+=a.z*b.y; acc[2][2]+=a.z*b.z; acc[2][3]+=a.z*b.w;
        acc[3][0]+=a.w*b.x; acc[3][1]+=a.w*b.y; acc[3][2]+=a.w*b.z; acc[3][3]+=a.w*b.w;
    }
    const float scale = 0.04419417382415922f;   // 1/sqrt(512)
    #pragma unroll
    for (int i = 0; i < 4; i++) {
        int s = s0 + ty * 4 + i;
        const float* psrow0 = ps + ((size_t)bh * Ss + s) * Ss;
        const float* psrow1 = psrow0 + Ss;      // row s+1 (only read when valid)
        float* o = sc + ((size_t)bh * Ss + s) * Ss + t0 + tx * 4;
        #pragma unroll
        for (int j = 0; j < 4; j++) {
            int tt = t0 + tx * 4 + j;
            float p;
            if (tt <= s)           p = psrow0[Ss - 1 - s + tt];
            else if (tt == s + 1)  p = 0.0f;
            else                   p = psrow1[tt - s - 2];
            o[j] = (acc[i][j] + p) * scale;
        }
    }
}

// ---------------- softmax over last axis (rows of 2048) ---------------------
__global__ void softmax_kernel(float* __restrict__ sc) {
    const size_t row = blockIdx.x;
    float4* p = (float4*)(sc + row * (size_t)Ss);
    const int t = threadIdx.x;                  // 256 threads x 8 elems
    float4 v0 = p[t], v1 = p[t + 256];
    float m = fmaxf(fmaxf(fmaxf(v0.x, v0.y), fmaxf(v0.z, v0.w)),
                    fmaxf(fmaxf(v1.x, v1.y), fmaxf(v1.z, v1.w)));
    #pragma unroll
    for (int o = 16; o; o >>= 1) m = fmaxf(m, __shfl_xor_sync(0xffffffffu, m, o));
    __shared__ float rm[8], rs[8];
    if ((t & 31) == 0) rm[t >> 5] = m;
    __syncthreads();
    float M = rm[0];
    #pragma unroll
    for (int i = 1; i < 8; i++) M = fmaxf(M, rm[i]);
    v0.x = __expf(v0.x - M); v0.y = __expf(v0.y - M);
    v0.z = __expf(v0.z - M); v0.w = __expf(v0.w - M);
    v1.x = __expf(v1.x - M); v1.y = __expf(v1.y - M);
    v1.z = __expf(v1.z - M); v1.w = __expf(v1.w - M);
    float s = v0.x + v0.y + v0.z + v0.w + v1.x + v1.y + v1.z + v1.w;
    #pragma unroll
    for (int o = 16; o; o >>= 1) s += __shfl_xor_sync(0xffffffffu, s, o);
    if ((t & 31) == 0) rs[t >> 5] = s;
    __syncthreads();
    float Sm = 0.f;
    #pragma unroll
    for (int i = 0; i < 8; i++) Sm += rs[i];
    float inv = 1.0f / Sm;
    v0.x *= inv; v0.y *= inv; v0.z *= inv; v0.w *= inv;
    v1.x *= inv; v1.y *= inv; v1.z *= inv; v1.w *= inv;
    p[t] = v0; p[t + 256] = v1;
}

// ---------------- ctx = attn @ v per (b,h):  [S,S] x [S,64] -----------------
__global__ void ctx_kernel(const float* __restrict__ attn,
                           const float* __restrict__ v,
                           float* __restrict__ ctx) {
    const int bh = blockIdx.z, b = bh >> 3, h = bh & 7;
    const int s0 = blockIdx.y * 64;
    __shared__ float As[16][64];   // [k][s]
    __shared__ float Bs[16][64];   // [k][d]
    const int t  = threadIdx.x;
    const int tx = t & 15, ty = t >> 4;
    const int lrow = t >> 2, lq = t & 3;
    const int vr = t >> 4, vc = t & 15;
    float acc[4][4] = {};
    const float* ap = attn + ((size_t)bh * Ss + s0 + lrow) * Ss + lq * 4;
    for (int k0 = 0; k0 < Ss; k0 += 16) {
        float4 av = *(const float4*)(ap + k0);
        As[lq*4+0][lrow] = av.x; As[lq*4+1][lrow] = av.y;
        As[lq*4+2][lrow] = av.z; As[lq*4+3][lrow] = av.w;
        float4 vv = *(const float4*)(v + ((size_t)(b * Ss + k0 + vr)) * Dd + h * 64 + vc * 4);
        *(float4*)&Bs[vr][vc * 4] = vv;
        __syncthreads();
        #pragma unroll
        for (int kk = 0; kk < 16; kk++) {
            float4 a = *(const float4*)&As[kk][ty * 4];
            float4 b2 = *(const float4*)&Bs[kk][tx * 4];
            acc[0][0]+=a.x*b2.x; acc[0][1]+=a.x*b2.y; acc[0][2]+=a.x*b2.z; acc[0][3]+=a.x*b2.w;
            acc[1][0]+=a.y*b2.x; acc[1][1]+=a.y*b2.y; acc[1][2]+=a.y*b2.z; acc[1][3]+=a.y*b2.w;
            acc[2][0]+=a.z*b2.x; acc[2][1]+=a.z*b2.y; acc[2][2]+=a.z*b2.z; acc[2][3]+=a.z*b2.w;
            acc[3][0]+=a.w*b2.x; acc[3][1]+=a.w*b2.y; acc[3][2]+=a.w*b2.z; acc[3][3]+=a.w*b2.w;
        }
        __syncthreads();
    }
    #pragma unroll
    for (int i = 0; i < 4; i++) {
        float* o = ctx + ((size_t)(b * Ss + s0 + ty * 4 + i)) * Dd + h * 64 + tx * 4;
        #pragma unroll
        for (int j = 0; j < 4; j++) o[j] = acc[i][j];
    }
}

// ---------------- launch -----------------------------------------------------
extern "C" void kernel_launch(void* const* d_in, const int* in_sizes, int n_in,
                              void* d_out, int out_size) {
    const float* inputs = (const float*)d_in[0];
    const float* gamma  = (const float*)d_in[1];
    const float* beta   = (const float*)d_in[2];
    const float* Wq     = (const float*)d_in[3];
    const float* bq     = (const float*)d_in[4];
    const float* Wk     = (const float*)d_in[5];
    const float* bk     = (const float*)d_in[6];
    const float* Wv     = (const float*)d_in[7];
    const float* bv     = (const float*)d_in[8];
    const float* Wpos   = (const float*)d_in[9];
    const float* ub     = (const float*)d_in[10];
    const float* vb     = (const float*)d_in[11];
    const float* Wo     = (const float*)d_in[12];
    const float* bo     = (const float*)d_in[13];
    float* out = (float*)d_out;

    float *xn, *q, *k, *v, *ctx, *pe, *pos, *ps, *sc;
    cudaGetSymbolAddress((void**)&xn,  g_xn);
    cudaGetSymbolAddress((void**)&q,   g_q);
    cudaGetSymbolAddress((void**)&k,   g_k);
    cudaGetSymbolAddress((void**)&v,   g_v);
    cudaGetSymbolAddress((void**)&ctx, g_ctx);
    cudaGetSymbolAddress((void**)&pe,  g_pe);
    cudaGetSymbolAddress((void**)&pos, g_pos);
    cudaGetSymbolAddress((void**)&ps,  g_ps);
    cudaGetSymbolAddress((void**)&sc,  g_sc);

    pe_kernel<<<2048, 256>>>(pe);
    ln_kernel<<<Bb * Ss, 256>>>(inputs, gamma, beta, xn);

    dim3 gp(512 / 64, 8192 / 64);     // N tiles x M tiles
    gemm_nt_bias<<<gp, 256>>>(xn, Wq, bq, q, 8192, 512, 512);
    gemm_nt_bias<<<gp, 256>>>(xn, Wk, bk, k, 8192, 512, 512);
    gemm_nt_bias<<<gp, 256>>>(xn, Wv, bv, v, 8192, 512, 512);
    gemm_nt_bias<<<dim3(8, 32), 256>>>(pe, Wpos, nullptr, pos, 2048, 512, 512);

    dim3 ga(32, 32, 32);              // t tiles, s tiles, b*h
    ps_kernel<<<ga, 256>>>(q, pos, vb, ps);
    score_kernel<<<ga, 256>>>(q, k, ub, ps, sc);
    softmax_kernel<<<Bb * Hh * Ss, 256>>>(sc);
    ctx_kernel<<<dim3(1, 32, 32), 256>>>(sc, v, ctx);
    gemm_nt_bias<<<gp, 256>>>(ctx, Wo, bo, out, 8192, 512, 512);
}

// round 2
// speedup vs baseline: 1.5817x; 1.5817x over previous
#include <cuda_runtime.h>
#include <mma.h>
#include <math.h>
using namespace nvcuda;

#define Bb 4
#define Ss 2048
#define Dd 512
#define Hh 8

// ---------------- scratch ---------------------------------------------------
__device__ float g_xn [Bb*Ss*Dd];
__device__ float g_q  [Bb*Ss*Dd];
__device__ float g_k  [Bb*Ss*Dd];
__device__ float g_v  [Bb*Ss*Dd];
__device__ float g_ctx[Bb*Ss*Dd];
__device__ float g_pe [Ss*Dd];
__device__ float g_pos[Ss*Dd];
__device__ float g_ps [(size_t)Bb*Hh*Ss*Ss];   // 512 MB
__device__ float g_sc [(size_t)Bb*Hh*Ss*Ss];   // 512 MB

__device__ __forceinline__ float f2t(float x) {
    unsigned r; asm("cvt.rna.tf32.f32 %0, %1;" : "=r"(r) : "f"(x));
    return __uint_as_float(r);
}

// ---------------- sinusoidal positional encoding ---------------------------
__global__ void pe_kernel(float* __restrict__ pe) {
    int idx = blockIdx.x * blockDim.x + threadIdx.x;
    int s = idx >> 8;
    int i = idx & 255;
    float div = expf((2.0f * (float)i) * (-9.210340371976184f / 512.0f));
    float a = (float)s * div;
    pe[s * Dd + 2 * i]     = sinf(a);
    pe[s * Dd + 2 * i + 1] = cosf(a);
}

// ---------------- layernorm -------------------------------------------------
__global__ void ln_kernel(const float* __restrict__ x,
                          const float* __restrict__ gamma,
                          const float* __restrict__ beta,
                          float* __restrict__ out) {
    int row = blockIdx.x;
    const float2* xr = (const float2*)(x + (size_t)row * Dd);
    int t = threadIdx.x;
    float2 v = xr[t];
    float s1 = v.x + v.y;
    float s2 = v.x * v.x + v.y * v.y;
    #pragma unroll
    for (int o = 16; o; o >>= 1) {
        s1 += __shfl_xor_sync(0xffffffffu, s1, o);
        s2 += __shfl_xor_sync(0xffffffffu, s2, o);
    }
    __shared__ float r1[8], r2[8];
    if ((t & 31) == 0) { r1[t >> 5] = s1; r2[t >> 5] = s2; }
    __syncthreads();
    float S1 = 0.f, S2 = 0.f;
    #pragma unroll
    for (int i = 0; i < 8; i++) { S1 += r1[i]; S2 += r2[i]; }
    float mean = S1 * (1.0f / 512.0f);
    float var  = S2 * (1.0f / 512.0f) - mean * mean;
    float rstd = rsqrtf(var + 1e-5f);
    float2 g  = ((const float2*)gamma)[t];
    float2 bt = ((const float2*)beta)[t];
    float2 o2;
    o2.x = (v.x - mean) * rstd * g.x + bt.x;
    o2.y = (v.y - mean) * rstd * g.y + bt.y;
    ((float2*)(out + (size_t)row * Dd))[t] = o2;
}

// ---------------- TF32 wmma: C = A @ W^T + bias -----------------------------
// A[M,K] row-major, W[N,K] row-major. Block tile 128x64, BK=32, 8 warps.
__global__ void __launch_bounds__(256) gemm_nt_wmma(
        const float* __restrict__ A, const float* __restrict__ W,
        const float* __restrict__ bias, float* __restrict__ C,
        int M, int N, int K) {
    __shared__ float sm[128 * 68];             // 34.8 KB; reused as staging
    float* As = sm;                             // [128][36]
    float* Bs = sm + 128 * 36;                  // [64][36]
    const int t = threadIdx.x;
    const int warp = t >> 5;
    const int wm = warp & 3, wn = warp >> 2;    // 4x2 warps, 32x32 each
    const int m0 = blockIdx.y * 128, n0 = blockIdx.x * 64;

    wmma::fragment<wmma::accumulator, 16, 16, 8, float> acc[2][2];
    #pragma unroll
    for (int i = 0; i < 2; i++)
        #pragma unroll
        for (int j = 0; j < 2; j++) wmma::fill_fragment(acc[i][j], 0.0f);

    for (int k0 = 0; k0 < K; k0 += 32) {
        #pragma unroll
        for (int i = 0; i < 4; i++) {
            int idx = i * 256 + t, row = idx >> 3, c = (idx & 7) * 4;
            float4 v = *(const float4*)(A + (size_t)(m0 + row) * K + k0 + c);
            float* d = &As[row * 36 + c];
            d[0] = f2t(v.x); d[1] = f2t(v.y); d[2] = f2t(v.z); d[3] = f2t(v.w);
        }
        #pragma unroll
        for (int i = 0; i < 2; i++) {
            int idx = i * 256 + t, row = idx >> 3, c = (idx & 7) * 4;
            float4 v = *(const float4*)(W + (size_t)(n0 + row) * K + k0 + c);
            float* d = &Bs[row * 36 + c];
            d[0] = f2t(v.x); d[1] = f2t(v.y); d[2] = f2t(v.z); d[3] = f2t(v.w);
        }
        __syncthreads();
        #pragma unroll
        for (int kk = 0; kk < 4; kk++) {
            wmma::fragment<wmma::matrix_a, 16, 16, 8, wmma::precision::tf32, wmma::row_major> a[2];
            wmma::fragment<wmma::matrix_b, 16, 16, 8, wmma::precision::tf32, wmma::col_major> b[2];
            wmma::load_matrix_sync(a[0], &As[(wm * 32) * 36 + kk * 8], 36);
            wmma::load_matrix_sync(a[1], &As[(wm * 32 + 16) * 36 + kk * 8], 36);
            wmma::load_matrix_sync(b[0], &Bs[(wn * 32) * 36 + kk * 8], 36);
            wmma::load_matrix_sync(b[1], &Bs[(wn * 32 + 16) * 36 + kk * 8], 36);
            #pragma unroll
            for (int i = 0; i < 2; i++)
                #pragma unroll
                for (int j = 0; j < 2; j++)
                    wmma::mma_sync(acc[i][j], a[i], b[j], acc[i][j]);
        }
        __syncthreads();
    }
    // stage to SMEM, then coalesced bias-add write
    #pragma unroll
    for (int i = 0; i < 2; i++)
        #pragma unroll
        for (int j = 0; j < 2; j++)
            wmma::store_matrix_sync(&sm[(wm * 32 + i * 16) * 68 + wn * 32 + j * 16],
                                    acc[i][j], 68, wmma::mem_row_major);
    __syncthreads();
    #pragma unroll
    for (int i = 0; i < 8; i++) {
        int idx = i * 256 + t, row = idx >> 4, c = (idx & 15) * 4;
        float4 o;
        float b0 = 0.f, b1 = 0.f, b2 = 0.f, b3 = 0.f;
        if (bias) { b0 = bias[n0+c]; b1 = bias[n0+c+1]; b2 = bias[n0+c+2]; b3 = bias[n0+c+3]; }
        o.x = sm[row * 68 + c]     + b0;
        o.y = sm[row * 68 + c + 1] + b1;
        o.z = sm[row * 68 + c + 2] + b2;
        o.w = sm[row * 68 + c + 3] + b3;
        *(float4*)(C + (size_t)(m0 + row) * N + n0 + c) = o;
    }
}

// ---------------- TF32 wmma: out[bh,s,t] = (q_s + hbias) . X_t --------------
// X = k (batched) for content, X = pos (shared) for PS. Tile 128x128, K=64.
__global__ void __launch_bounds__(256) qk_wmma(
        const float* __restrict__ q, const float* __restrict__ X, int x_batched,
        const float* __restrict__ hbias, float* __restrict__ out) {
    __shared__ float sm[2 * 128 * 36];          // 36.9 KB
    float* Qs = sm;                              // [128][36]
    float* Ks = sm + 128 * 36;                   // [128][36]
    const int t = threadIdx.x;
    const int warp = t >> 5;
    const int wm = warp & 1, wn = warp >> 1;     // 2x4 warps, 64x32 each
    const int bh = blockIdx.z, b = bh >> 3, h = bh & 7;
    const int s0 = blockIdx.y * 128, t0 = blockIdx.x * 128;
    const float* Xb = X + (x_batched ? (size_t)b * Ss * Dd : 0);

    wmma::fragment<wmma::accumulator, 16, 16, 8, float> acc[4][2];
    #pragma unroll
    for (int i = 0; i < 4; i++)
        #pragma unroll
        for (int j = 0; j < 2; j++) wmma::fill_fragment(acc[i][j], 0.0f);

    #pragma unroll
    for (int kc = 0; kc < 2; kc++) {
        const int koff = h * 64 + kc * 32;
        #pragma unroll
        for (int i = 0; i < 4; i++) {
            int idx = i * 256 + t, row = idx >> 3, c = (idx & 7) * 4;
            float4 v = *(const float4*)(q + (size_t)(b * Ss + s0 + row) * Dd + koff + c);
            const float* bb = &hbias[h * 64 + kc * 32 + c];
            float* d = &Qs[row * 36 + c];
            d[0] = f2t(v.x + bb[0]); d[1] = f2t(v.y + bb[1]);
            d[2] = f2t(v.z + bb[2]); d[3] = f2t(v.w + bb[3]);
        }
        #pragma unroll
        for (int i = 0; i < 4; i++) {
            int idx = i * 256 + t, row = idx >> 3, c = (idx & 7) * 4;
            float4 v = *(const float4*)(Xb + (size_t)(t0 + row) * Dd + koff + c);
            float* d = &Ks[row * 36 + c];
            d[0] = f2t(v.x); d[1] = f2t(v.y); d[2] = f2t(v.z); d[3] = f2t(v.w);
        }
        __syncthreads();
        #pragma unroll
        for (int kk = 0; kk < 4; kk++) {
            wmma::fragment<wmma::matrix_a, 16, 16, 8, wmma::precision::tf32, wmma::row_major> a[4];
            wmma::fragment<wmma::matrix_b, 16, 16, 8, wmma::precision::tf32, wmma::col_major> bf[2];
            #pragma unroll
            for (int i = 0; i < 4; i++)
                wmma::load_matrix_sync(a[i], &Qs[(wm * 64 + i * 16) * 36 + kk * 8], 36);
            #pragma unroll
            for (int j = 0; j < 2; j++)
                wmma::load_matrix_sync(bf[j], &Ks[(wn * 32 + j * 16) * 36 + kk * 8], 36);
            #pragma unroll
            for (int i = 0; i < 4; i++)
                #pragma unroll
                for (int j = 0; j < 2; j++)
                    wmma::mma_sync(acc[i][j], a[i], bf[j], acc[i][j]);
        }
        __syncthreads();
    }
    #pragma unroll
    for (int i = 0; i < 4; i++)
        #pragma unroll
        for (int j = 0; j < 2; j++)
            wmma::store_matrix_sync(
                out + ((size_t)bh * Ss + s0 + wm * 64 + i * 16) * Ss + t0 + wn * 32 + j * 16,
                acc[i][j], Ss, wmma::mem_row_major);
}

// ---------------- fused rel_shift + scale + softmax (in place on sc) --------
// shifted[s,t] = PS[s, S-1-s+t] for t<=s ; 0 for t==s+1 ; PS[s+1, t-s-2] else
__global__ void __launch_bounds__(256) softmax_shift(
        float* __restrict__ sc, const float* __restrict__ ps) {
    const size_t row = blockIdx.x;              // bh*S + s
    const int s = (int)(row & (Ss - 1));
    float* base = sc + row * (size_t)Ss;
    const float* p0 = ps + row * (size_t)Ss;    // PS row s (same bh)
    const float* p1 = p0 + Ss;                  // PS row s+1 (only read if valid)
    const int t = threadIdx.x;
    const int c0 = t * 8;
    float4 a = *(float4*)(base + c0);
    float4 bql = *(float4*)(base + c0 + 4);
    float vals[8] = {a.x, a.y, a.z, a.w, bql.x, bql.y, bql.z, bql.w};
    const float scale = 0.04419417382415922f;   // 1/sqrt(512)
    #pragma unroll
    for (int j = 0; j < 8; j++) {
        int tt = c0 + j;
        float p;
        if (tt <= s)          p = p0[Ss - 1 - s + tt];
        else if (tt == s + 1) p = 0.0f;
        else                  p = p1[tt - s - 2];
        vals[j] = (vals[j] + p) * scale;
    }
    float m = vals[0];
    #pragma unroll
    for (int j = 1; j < 8; j++) m = fmaxf(m, vals[j]);
    #pragma unroll
    for (int o = 16; o; o >>= 1) m = fmaxf(m, __shfl_xor_sync(0xffffffffu, m, o));
    __shared__ float rm[8], rs[8];
    if ((t & 31) == 0) rm[t >> 5] = m;
    __syncthreads();
    float M = rm[0];
    #pragma unroll
    for (int i = 1; i < 8; i++) M = fmaxf(M, rm[i]);
    float sum = 0.f;
    #pragma unroll
    for (int j = 0; j < 8; j++) { vals[j] = __expf(vals[j] - M); sum += vals[j]; }
    #pragma unroll
    for (int o = 16; o; o >>= 1) sum += __shfl_xor_sync(0xffffffffu, sum, o);
    if ((t & 31) == 0) rs[t >> 5] = sum;
    __syncthreads();
    float Sm = 0.f;
    #pragma unroll
    for (int i = 0; i < 8; i++) Sm += rs[i];
    float inv = 1.0f / Sm;
    a.x = vals[0]*inv; a.y = vals[1]*inv; a.z = vals[2]*inv; a.w = vals[3]*inv;
    bql.x = vals[4]*inv; bql.y = vals[5]*inv; bql.z = vals[6]*inv; bql.w = vals[7]*inv;
    *(float4*)(base + c0)     = a;
    *(float4*)(base + c0 + 4) = bql;
}

// ---------------- TF32 wmma: ctx = attn @ v per (b,h) -----------------------
__global__ void __launch_bounds__(256) ctx_wmma(
        const float* __restrict__ attn, const float* __restrict__ v,
        float* __restrict__ ctx) {
    __shared__ float sm[128 * 36 + 32 * 68];    // 27.1 KB
    float* As = sm;                              // [128][36]
    float* Bs = sm + 128 * 36;                   // [32][68]
    const int t = threadIdx.x;
    const int warp = t >> 5;
    const int wm = warp & 3, wn = warp >> 2;     // 4x2 warps, 32x32 each
    const int bh = blockIdx.z, b = bh >> 3, h = bh & 7;
    const int s0 = blockIdx.y * 128;

    wmma::fragment<wmma::accumulator, 16, 16, 8, float> acc[2][2];
    #pragma unroll
    for (int i = 0; i < 2; i++)
        #pragma unroll
        for (int j = 0; j < 2; j++) wmma::fill_fragment(acc[i][j], 0.0f);

    for (int k0 = 0; k0 < Ss; k0 += 32) {
        #pragma unroll
        for (int i = 0; i < 4; i++) {
            int idx = i * 256 + t, row = idx >> 3, c = (idx & 7) * 4;
            float4 av = *(const float4*)(attn + ((size_t)bh * Ss + s0 + row) * Ss + k0 + c);
            float* d = &As[row * 36 + c];
            d[0] = f2t(av.x); d[1] = f2t(av.y); d[2] = f2t(av.z); d[3] = f2t(av.w);
        }
        #pragma unroll
        for (int i = 0; i < 2; i++) {
            int idx = i * 256 + t, kr = idx >> 4, c = (idx & 15) * 4;
            float4 vv = *(const float4*)(v + (size_t)(b * Ss + k0 + kr) * Dd + h * 64 + c);
            float* d = &Bs[kr * 68 + c];
            d[0] = f2t(vv.x); d[1] = f2t(vv.y); d[2] = f2t(vv.z); d[3] = f2t(vv.w);
        }
        __syncthreads();
        #pragma unroll
        for (int kk = 0; kk < 4; kk++) {
            wmma::fragment<wmma::matrix_a, 16, 16, 8, wmma::precision::tf32, wmma::row_major> a[2];
            wmma::fragment<wmma::matrix_b, 16, 16, 8, wmma::precision::tf32, wmma::row_major> bf[2];
            #pragma unroll
            for (int i = 0; i < 2; i++)
                wmma::load_matrix_sync(a[i], &As[(wm * 32 + i * 16) * 36 + kk * 8], 36);
            #pragma unroll
            for (int j = 0; j < 2; j++)
                wmma::load_matrix_sync(bf[j], &Bs[(kk * 8) * 68 + wn * 32 + j * 16], 68);
            #pragma unroll
            for (int i = 0; i < 2; i++)
                #pragma unroll
                for (int j = 0; j < 2; j++)
                    wmma::mma_sync(acc[i][j], a[i], bf[j], acc[i][j]);
        }
        __syncthreads();
    }
    #pragma unroll
    for (int i = 0; i < 2; i++)
        #pragma unroll
        for (int j = 0; j < 2; j++)
            wmma::store_matrix_sync(
                ctx + (size_t)(b * Ss + s0 + wm * 32 + i * 16) * Dd + h * 64 + wn * 32 + j * 16,
                acc[i][j], Dd, wmma::mem_row_major);
}

// ---------------- launch -----------------------------------------------------
extern "C" void kernel_launch(void* const* d_in, const int* in_sizes, int n_in,
                              void* d_out, int out_size) {
    const float* inputs = (const float*)d_in[0];
    const float* gamma  = (const float*)d_in[1];
    const float* beta   = (const float*)d_in[2];
    const float* Wq     = (const float*)d_in[3];
    const float* bq     = (const float*)d_in[4];
    const float* Wk     = (const float*)d_in[5];
    const float* bk     = (const float*)d_in[6];
    const float* Wv     = (const float*)d_in[7];
    const float* bv     = (const float*)d_in[8];
    const float* Wpos   = (const float*)d_in[9];
    const float* ub     = (const float*)d_in[10];
    const float* vb     = (const float*)d_in[11];
    const float* Wo     = (const float*)d_in[12];
    const float* bo     = (const float*)d_in[13];
    float* out = (float*)d_out;

    float *xn, *q, *k, *v, *ctx, *pe, *pos, *ps, *sc;
    cudaGetSymbolAddress((void**)&xn,  g_xn);
    cudaGetSymbolAddress((void**)&q,   g_q);
    cudaGetSymbolAddress((void**)&k,   g_k);
    cudaGetSymbolAddress((void**)&v,   g_v);
    cudaGetSymbolAddress((void**)&ctx, g_ctx);
    cudaGetSymbolAddress((void**)&pe,  g_pe);
    cudaGetSymbolAddress((void**)&pos, g_pos);
    cudaGetSymbolAddress((void**)&ps,  g_ps);
    cudaGetSymbolAddress((void**)&sc,  g_sc);

    pe_kernel<<<2048, 256>>>(pe);
    ln_kernel<<<Bb * Ss, 256>>>(inputs, gamma, beta, xn);

    gemm_nt_wmma<<<dim3(8, 64), 256>>>(xn, Wq, bq, q, 8192, 512, 512);
    gemm_nt_wmma<<<dim3(8, 64), 256>>>(xn, Wk, bk, k, 8192, 512, 512);
    gemm_nt_wmma<<<dim3(8, 64), 256>>>(xn, Wv, bv, v, 8192, 512, 512);
    gemm_nt_wmma<<<dim3(8, 16), 256>>>(pe, Wpos, nullptr, pos, 2048, 512, 512);

    qk_wmma<<<dim3(16, 16, 32), 256>>>(q, k,   1, ub, sc);   // content scores
    qk_wmma<<<dim3(16, 16, 32), 256>>>(q, pos, 0, vb, ps);   // position scores

    softmax_shift<<<Bb * Hh * Ss, 256>>>(sc, ps);            // shift+scale+softmax

    ctx_wmma<<<dim3(1, 16, 32), 256>>>(sc, v, ctx);
    gemm_nt_wmma<<<dim3(8, 64), 256>>>(ctx, Wo, bo, out, 8192, 512, 512);
}